// round 1
// baseline (speedup 1.0000x reference)
#include <cuda_runtime.h>
#include <math.h>

#define NHYP 64
#define D 320
#define NH 4
#define HD 80
#define HALF 40
#define TK 256
#define TCACHE 255
#define FF 2048
#define NL 5

// ---------------- scratch (device globals; no allocation allowed) ----------------
__device__ float g_tgt[NHYP * D];
__device__ float g_nt[NHYP * D];
__device__ float g_nc[NHYP * TK * D];   // LN'd combined (self-attn K/V source)
__device__ float g_k[NHYP * TK * D];    // rotated K (self or cross)
__device__ float g_q[NHYP * D];         // rotated, scaled q
__device__ float g_y[NHYP * NH * D];    // p @ X per head
__device__ float g_ff[NHYP * FF];
__device__ float g_rotc[TK * HALF];     // k-side xPos cos*scale
__device__ float g_rots[TK * HALF];     // k-side xPos sin*scale
__device__ float g_qc[HALF];            // q-side factors
__device__ float g_qs[HALF];

// ---------------- block reductions (blockDim.x == 320, 10 warps) ----------------
__device__ __forceinline__ float bsum(float v, float* buf, int nw) {
#pragma unroll
    for (int o = 16; o; o >>= 1) v += __shfl_down_sync(0xffffffffu, v, o);
    if ((threadIdx.x & 31) == 0) buf[threadIdx.x >> 5] = v;
    __syncthreads();
    if (threadIdx.x == 0) {
        float s = 0.f;
        for (int i = 0; i < nw; i++) s += buf[i];
        buf[0] = s;
    }
    __syncthreads();
    float r = buf[0];
    __syncthreads();
    return r;
}

__device__ __forceinline__ float bmax(float v, float* buf, int nw) {
#pragma unroll
    for (int o = 16; o; o >>= 1) v = fmaxf(v, __shfl_down_sync(0xffffffffu, v, o));
    if ((threadIdx.x & 31) == 0) buf[threadIdx.x >> 5] = v;
    __syncthreads();
    if (threadIdx.x == 0) {
        float s = -1e30f;
        for (int i = 0; i < nw; i++) s = fmaxf(s, buf[i]);
        buf[0] = s;
    }
    __syncthreads();
    float r = buf[0];
    __syncthreads();
    return r;
}

// ---------------- xPos factor tables ----------------
// k-side: L=256, offset 0, downscale=True  -> scale = base^{-(t-128)/320}
// q-side: L=1, offset=q_offset, downscale=False, pos = q_offset
__global__ void k_tables(const int* __restrict__ qoff) {
    int e = blockIdx.x * blockDim.x + threadIdx.x;
    if (e < TK * HALF) {
        int t = e / HALF, i = e % HALF;
        float bs = (2.0f * i + 0.4f * HD) / (1.4f * HD);
        float invf = powf(10000.0f, -(float)i / HALF);
        float power = ((float)t - 128.0f) / 320.0f;   // min_pos = -128 for total=256
        float z = powf(bs, -power);                   // downscale -> inverse
        float th = (float)t * invf;
        g_rotc[e] = cosf(th) * z;
        g_rots[e] = sinf(th) * z;
    } else if (e < TK * HALF + HALF) {
        int i = e - TK * HALF;
        int off = qoff[0];
        int total = off + 1;
        int minp = -((total + 1) >> 1);               // floor(-total/2)
        float bs = (2.0f * i + 0.4f * HD) / (1.4f * HD);
        float invf = powf(10000.0f, -(float)i / HALF);
        float pq = (float)(minp + total - 1) / 320.0f;
        float z = powf(bs, pq);
        float th = (float)(total - 1) * invf;
        g_qc[i] = cosf(th) * z;
        g_qs[i] = sinf(th) * z;
    }
}

// ---------------- embedding gather ----------------
__global__ void k_embed(const int* __restrict__ toks, const float* __restrict__ table) {
    int h = blockIdx.x, d = threadIdx.x;
    g_tgt[h * D + d] = table[(long)toks[h] * D + d];
}

// ---------------- LN over combined [cache; tgt] ----------------
__global__ void k_ln_combined(const float* __restrict__ cache_l,
                              const float* __restrict__ w, const float* __restrict__ b) {
    __shared__ float buf[10];
    int t = blockIdx.x, h = blockIdx.y, d = threadIdx.x;
    float v = (t < TCACHE) ? cache_l[((long)h * TCACHE + t) * D + d] : g_tgt[h * D + d];
    float mu = bsum(v, buf, 10) * (1.0f / D);
    float dv = v - mu;
    float var = bsum(dv * dv, buf, 10) * (1.0f / D);
    g_nc[((long)h * TK + t) * D + d] = dv * rsqrtf(var + 1e-5f) * w[d] + b[d];
}

// ---------------- LN over tgt only -> g_nt ----------------
__global__ void k_ln_vec(const float* __restrict__ w, const float* __restrict__ b) {
    __shared__ float buf[10];
    int h = blockIdx.x, d = threadIdx.x;
    float v = g_tgt[h * D + d];
    float mu = bsum(v, buf, 10) * (1.0f / D);
    float dv = v - mu;
    float var = bsum(dv * dv, buf, 10) * (1.0f / D);
    g_nt[h * D + d] = dv * rsqrtf(var + 1e-5f) * w[d] + b[d];
}

// ---------------- q projection + scale + xPos (q-side) ----------------
__global__ void k_qproj(int cross, const float* __restrict__ W, const float* __restrict__ bias) {
    __shared__ float xs[D];
    __shared__ float qt[D];
    int h = blockIdx.x, n = threadIdx.x;
    xs[n] = cross ? g_nt[h * D + n] : g_nc[((long)h * TK + TCACHE) * D + n];
    __syncthreads();
    float acc = bias[n];
    for (int k = 0; k < D; k++) acc += xs[k] * W[k * D + n];
    qt[n] = acc * 0.11180339887498949f;   // 80^-0.5
    __syncthreads();
    int p = (n % HD) >> 1;
    float c = g_qc[p], s = g_qs[p];
    float e = qt[n & ~1], o = qt[n | 1];
    g_q[h * D + n] = (n & 1) ? (o * c + e * s) : (e * c - o * s);
}

// ---------------- K projection GEMM [16384,320]@[320,320] + bias + xPos (k-side) ----------------
#define BM 64
#define BN 64
#define BK 32
__global__ void __launch_bounds__(256) k_gemm_rot(const float* __restrict__ Aext, int useExt,
                                                  const float* __restrict__ B,
                                                  const float* __restrict__ bias) {
    __shared__ float As[BM][BK + 1];
    __shared__ float Bs[BK][BN];
    const float* A = useExt ? Aext : g_nc;
    int m0 = blockIdx.x * BM;
    int n0 = blockIdx.y * BN;
    int tid = threadIdx.x;
    int tx = tid & 15, ty = tid >> 4;
    float acc[4][4] = {};
    for (int k0 = 0; k0 < D; k0 += BK) {
        {
            int row = tid >> 3;
            int cg = (tid & 7) * 4;
            float4 a0 = *(const float4*)&A[(long)(m0 + row) * D + k0 + cg];
            float4 a1 = *(const float4*)&A[(long)(m0 + row + 32) * D + k0 + cg];
            As[row][cg + 0] = a0.x; As[row][cg + 1] = a0.y;
            As[row][cg + 2] = a0.z; As[row][cg + 3] = a0.w;
            As[row + 32][cg + 0] = a1.x; As[row + 32][cg + 1] = a1.y;
            As[row + 32][cg + 2] = a1.z; As[row + 32][cg + 3] = a1.w;
            int brow = tid >> 4;
            int bcg = (tid & 15) * 4;
            *(float4*)&Bs[brow][bcg]      = *(const float4*)&B[(k0 + brow) * D + n0 + bcg];
            *(float4*)&Bs[brow + 16][bcg] = *(const float4*)&B[(k0 + brow + 16) * D + n0 + bcg];
        }
        __syncthreads();
#pragma unroll
        for (int kk = 0; kk < BK; kk++) {
            float a0 = As[ty * 4 + 0][kk];
            float a1 = As[ty * 4 + 1][kk];
            float a2 = As[ty * 4 + 2][kk];
            float a3 = As[ty * 4 + 3][kk];
            float4 b4 = *(const float4*)&Bs[kk][tx * 4];
            acc[0][0] += a0 * b4.x; acc[0][1] += a0 * b4.y; acc[0][2] += a0 * b4.z; acc[0][3] += a0 * b4.w;
            acc[1][0] += a1 * b4.x; acc[1][1] += a1 * b4.y; acc[1][2] += a1 * b4.z; acc[1][3] += a1 * b4.w;
            acc[2][0] += a2 * b4.x; acc[2][1] += a2 * b4.y; acc[2][2] += a2 * b4.z; acc[2][3] += a2 * b4.w;
            acc[3][0] += a3 * b4.x; acc[3][1] += a3 * b4.y; acc[3][2] += a3 * b4.z; acc[3][3] += a3 * b4.w;
        }
        __syncthreads();
    }
#pragma unroll
    for (int i = 0; i < 4; i++) {
        int m = m0 + ty * 4 + i;
        int t = m & (TK - 1);
#pragma unroll
        for (int j = 0; j < 4; j += 2) {
            int nn = n0 + tx * 4 + j;
            float e = acc[i][j] + bias[nn];
            float o = acc[i][j + 1] + bias[nn + 1];
            int p = (nn % HD) >> 1;
            float c = g_rotc[t * HALF + p], s = g_rots[t * HALF + p];
            g_k[(long)m * D + nn]     = e * c - o * s;
            g_k[(long)m * D + nn + 1] = o * c + e * s;
        }
    }
}

// ---------------- attention: scores + softmax + y = p @ X (V-trick) ----------------
__global__ void k_attn(const float* __restrict__ Xext, int useExt,
                       const unsigned char* __restrict__ mask) {
    __shared__ float qsm[D];
    __shared__ float p[NH][TK];
    __shared__ float buf[10];
    const float* X = useExt ? Xext : g_nc;
    int h = blockIdx.x, tid = threadIdx.x;
    qsm[tid] = g_q[h * D + tid];
    __syncthreads();
    if (tid < TK) {
        const float* krow = &g_k[((long)h * TK + tid) * D];
        bool msk = (mask != nullptr) && (mask[h * TK + tid] != 0);
#pragma unroll
        for (int hh = 0; hh < NH; hh++) {
            float a = 0.f;
#pragma unroll 8
            for (int d = 0; d < HD; d++) a += qsm[hh * HD + d] * krow[hh * HD + d];
            p[hh][tid] = msk ? -1e30f : a;
        }
    }
    __syncthreads();
    for (int hh = 0; hh < NH; hh++) {
        float lv = (tid < TK) ? p[hh][tid] : -1e30f;
        float mx = bmax(lv, buf, 10);
        float ex = (tid < TK) ? expf(lv - mx) : 0.f;
        float sm = bsum(ex, buf, 10);
        if (tid < TK) p[hh][tid] = ex / sm;
        __syncthreads();
    }
    float a0 = 0.f, a1 = 0.f, a2 = 0.f, a3 = 0.f;
    const float* xp = &X[(long)h * TK * D + tid];
    for (int t = 0; t < TK; t++) {
        float xv = xp[(long)t * D];
        a0 += p[0][t] * xv; a1 += p[1][t] * xv; a2 += p[2][t] * xv; a3 += p[3][t] * xv;
    }
    g_y[(h * NH + 0) * D + tid] = a0;
    g_y[(h * NH + 1) * D + tid] = a1;
    g_y[(h * NH + 2) * D + tid] = a2;
    g_y[(h * NH + 3) * D + tid] = a3;
}

// ---------------- z = y @ Wv(+bv) per head slice; out = z @ Wo + bo; tgt += out ----------------
__global__ void k_outproj(const float* __restrict__ Wv, const float* __restrict__ bv,
                          const float* __restrict__ Wo, const float* __restrict__ bo) {
    __shared__ float ys[NH * D];
    __shared__ float zs[D];
    int h = blockIdx.x, n = threadIdx.x;
    for (int i = n; i < NH * D; i += D) ys[i] = g_y[h * NH * D + i];
    __syncthreads();
    int hh = n / HD;
    float z = bv[n];
    for (int d2 = 0; d2 < D; d2++) z += ys[hh * D + d2] * Wv[d2 * D + n];
    zs[n] = z;
    __syncthreads();
    float o = bo[n];
    for (int m = 0; m < D; m++) o += zs[m] * Wo[m * D + n];
    g_tgt[h * D + n] += o;
}

// ---------------- feed-forward ----------------
__global__ void k_ff1(const float* __restrict__ W1, const float* __restrict__ b1) {
    __shared__ float xs[D];
    int h = blockIdx.y;
    int n = blockIdx.x * 256 + threadIdx.x;
    for (int i = threadIdx.x; i < D; i += 256) xs[i] = g_nt[h * D + i];
    __syncthreads();
    float acc = b1[n];
    for (int k = 0; k < D; k++) acc += xs[k] * W1[(long)k * FF + n];
    g_ff[h * FF + n] = fmaxf(acc, 0.f);
}

__global__ void k_ff2(const float* __restrict__ W2, const float* __restrict__ b2) {
    __shared__ float hs[FF];
    int h = blockIdx.x, n = threadIdx.x;
    for (int i = n; i < FF; i += D) hs[i] = g_ff[h * FF + i];
    __syncthreads();
    float acc = b2[n];
    for (int k = 0; k < FF; k++) acc += hs[k] * W2[(long)k * D + n];
    g_tgt[h * D + n] += acc;
}

__global__ void k_copy_out(float* __restrict__ out) {
    out[blockIdx.x * D + threadIdx.x] = g_tgt[blockIdx.x * D + threadIdx.x];
}

// ---------------- launch ----------------
extern "C" void kernel_launch(void* const* d_in, const int* in_sizes, int n_in,
                              void* d_out, int out_size) {
    const int* toks            = (const int*)d_in[0];
    const float* cached        = (const float*)d_in[1];
    const float* memory        = (const float*)d_in[2];
    const unsigned char* mmask = (const unsigned char*)d_in[3];
    const int* qoff            = (const int*)d_in[4];
    const float* table         = (const float*)d_in[5];
    const float* ln_w          = (const float*)d_in[6];
    const float* ln_b          = (const float*)d_in[7];
    const float* sa_w          = (const float*)d_in[8];
    const float* sa_b          = (const float*)d_in[9];
    const float* ca_w          = (const float*)d_in[10];
    const float* ca_b          = (const float*)d_in[11];
    const float* ff1w          = (const float*)d_in[12];
    const float* ff1b          = (const float*)d_in[13];
    const float* ff2w          = (const float*)d_in[14];
    const float* ff2b          = (const float*)d_in[15];

    k_tables<<<41, 256>>>(qoff);
    k_embed<<<NHYP, D>>>(toks, table);

    for (int l = 0; l < NL; l++) {
        const float* lw = ln_w + l * 3 * D;
        const float* lb = ln_b + l * 3 * D;
        const float* sw = sa_w + (long)l * 4 * D * D;
        const float* sb = sa_b + l * 4 * D;
        const float* cw = ca_w + (long)l * 4 * D * D;
        const float* cb = ca_b + l * 4 * D;

        // ---- self-attention ----
        k_ln_combined<<<dim3(TK, NHYP), D>>>(cached + (long)l * NHYP * TCACHE * D, lw, lb);
        k_qproj<<<NHYP, D>>>(0, sw + 0 * D * D, sb + 0 * D);
        k_gemm_rot<<<dim3(256, 5), 256>>>(nullptr, 0, sw + 1 * D * D, sb + 1 * D);
        k_attn<<<NHYP, D>>>(nullptr, 0, nullptr);
        k_outproj<<<NHYP, D>>>(sw + 2 * D * D, sb + 2 * D, sw + 3 * D * D, sb + 3 * D);

        // ---- cross-attention ----
        k_ln_vec<<<NHYP, D>>>(lw + D, lb + D);
        k_qproj<<<NHYP, D>>>(1, cw + 0 * D * D, cb + 0 * D);
        k_gemm_rot<<<dim3(256, 5), 256>>>(memory, 1, cw + 1 * D * D, cb + 1 * D);
        k_attn<<<NHYP, D>>>(memory, 1, mmask);
        k_outproj<<<NHYP, D>>>(cw + 2 * D * D, cb + 2 * D, cw + 3 * D * D, cb + 3 * D);

        // ---- feed-forward ----
        k_ln_vec<<<NHYP, D>>>(lw + 2 * D, lb + 2 * D);
        k_ff1<<<dim3(FF / 256, NHYP), 256>>>(ff1w + (long)l * D * FF, ff1b + l * FF);
        k_ff2<<<NHYP, D>>>(ff2w + (long)l * FF * D, ff2b + l * D);
    }
    k_copy_out<<<NHYP, D>>>((float*)d_out);
}

// round 3
// speedup vs baseline: 1.3325x; 1.3325x over previous
#include <cuda_runtime.h>
#include <math.h>
#include <stdint.h>

#define NHYP 64
#define D 320
#define NH 4
#define HD 80
#define HALF 40
#define TK 256
#define TCACHE 255
#define FF 2048
#define NL 5

// ---------------- scratch (device globals; no allocation allowed) ----------------
__device__ float g_tgt[NHYP * D];
__device__ float g_nt0[NHYP * D];       // LN(tgt, ln0)  (self q src + combined row 255)
__device__ float g_nt[NHYP * D];        // LN(tgt, ln1/ln2)
__device__ float g_k[NHYP * TK * D];    // rotated K
__device__ float g_q[NHYP * D];         // rotated, scaled q
__device__ float g_y[NHYP * NH * D];    // p @ X per head
__device__ float g_ff[NHYP * FF];
__device__ float g_mu[NL * NHYP * TCACHE];
__device__ float g_rs[NL * NHYP * TCACHE];
__device__ float g_rotc[TK * HALF];
__device__ float g_rots[TK * HALF];
__device__ float g_qc[HALF];
__device__ float g_qs[HALF];

// ---------------- helpers ----------------
__device__ __forceinline__ float bsum(float v, float* buf, int nw) {
#pragma unroll
    for (int o = 16; o; o >>= 1) v += __shfl_down_sync(0xffffffffu, v, o);
    if ((threadIdx.x & 31) == 0) buf[threadIdx.x >> 5] = v;
    __syncthreads();
    if (threadIdx.x == 0) {
        float s = 0.f;
        for (int i = 0; i < nw; i++) s += buf[i];
        buf[0] = s;
    }
    __syncthreads();
    float r = buf[0];
    __syncthreads();
    return r;
}
__device__ __forceinline__ float bmax(float v, float* buf, int nw) {
#pragma unroll
    for (int o = 16; o; o >>= 1) v = fmaxf(v, __shfl_down_sync(0xffffffffu, v, o));
    if ((threadIdx.x & 31) == 0) buf[threadIdx.x >> 5] = v;
    __syncthreads();
    if (threadIdx.x == 0) {
        float s = -1e30f;
        for (int i = 0; i < nw; i++) s = fmaxf(s, buf[i]);
        buf[0] = s;
    }
    __syncthreads();
    float r = buf[0];
    __syncthreads();
    return r;
}
__device__ __forceinline__ uint32_t f2tf(float f) {
    uint32_t u;
    asm("cvt.rna.tf32.f32 %0, %1;" : "=r"(u) : "f"(f));
    return u;
}
__device__ __forceinline__ void mma_tf32(float* d, const uint32_t* a, const uint32_t* b) {
    asm volatile(
        "mma.sync.aligned.m16n8k8.row.col.f32.tf32.tf32.f32 "
        "{%0,%1,%2,%3}, {%4,%5,%6,%7}, {%8,%9}, {%0,%1,%2,%3};"
        : "+f"(d[0]), "+f"(d[1]), "+f"(d[2]), "+f"(d[3])
        : "r"(a[0]), "r"(a[1]), "r"(a[2]), "r"(a[3]), "r"(b[0]), "r"(b[1]));
}

// ---------------- xPos tables ----------------
__global__ void k_tables(const int* __restrict__ qoff) {
    int e = blockIdx.x * blockDim.x + threadIdx.x;
    if (e < TK * HALF) {
        int t = e / HALF, i = e % HALF;
        float bs = (2.0f * i + 0.4f * HD) / (1.4f * HD);
        float invf = powf(10000.0f, -(float)i / HALF);
        float power = ((float)t - 128.0f) / 320.0f;
        float z = powf(bs, -power);
        float th = (float)t * invf;
        g_rotc[e] = cosf(th) * z;
        g_rots[e] = sinf(th) * z;
    } else if (e < TK * HALF + HALF) {
        int i = e - TK * HALF;
        int off = qoff[0];
        int total = off + 1;
        int minp = -((total + 1) >> 1);
        float bs = (2.0f * i + 0.4f * HD) / (1.4f * HD);
        float invf = powf(10000.0f, -(float)i / HALF);
        float pq = (float)(minp + total - 1) / 320.0f;
        float z = powf(bs, pq);
        float th = (float)(total - 1) * invf;
        g_qc[i] = cosf(th) * z;
        g_qs[i] = sinf(th) * z;
    }
}

__global__ void k_embed(const int* __restrict__ toks, const float* __restrict__ table) {
    int h = blockIdx.x, d = threadIdx.x;
    g_tgt[h * D + d] = table[(long)toks[h] * D + d];
}

// ---------------- per-row LN stats for all layers' caches ----------------
__global__ void k_rowstats(const float* __restrict__ cached) {
    int row = blockIdx.x * 8 + (threadIdx.x >> 5);
    if (row >= NL * NHYP * TCACHE) return;
    int lane = threadIdx.x & 31;
    const float* p = cached + (long)row * D;
    float s = 0.f, s2 = 0.f;
    for (int j = lane; j < D; j += 32) {
        float v = p[j];
        s += v;
        s2 += v * v;
    }
#pragma unroll
    for (int o = 16; o; o >>= 1) {
        s += __shfl_xor_sync(0xffffffffu, s, o);
        s2 += __shfl_xor_sync(0xffffffffu, s2, o);
    }
    if (lane == 0) {
        float mu = s * (1.0f / D);
        float var = s2 * (1.0f / D) - mu * mu;
        g_mu[row] = mu;
        g_rs[row] = rsqrtf(var + 1e-5f);
    }
}

// ---------------- LN of tgt -> g_nt0 (which==0) or g_nt (which==1) ----------------
__global__ void k_ln_vec(const float* __restrict__ w, const float* __restrict__ b, int which) {
    __shared__ float buf[10];
    int h = blockIdx.x, d = threadIdx.x;
    float v = g_tgt[h * D + d];
    float mu = bsum(v, buf, 10) * (1.0f / D);
    float dv = v - mu;
    float var = bsum(dv * dv, buf, 10) * (1.0f / D);
    float r = dv * rsqrtf(var + 1e-5f) * w[d] + b[d];
    if (which == 0) g_nt0[h * D + d] = r;
    else            g_nt[h * D + d] = r;
}

// ---------------- q projection ----------------
// grid (64, 2), block (160, 4); src: 0 -> g_nt0, 1 -> g_nt
__global__ void k_qproj(int srcsel, const float* __restrict__ W, const float* __restrict__ bias) {
    __shared__ float xs[D];
    __shared__ float part[4][160];
    __shared__ float qv[160];
    const float* src = srcsel ? g_nt : g_nt0;
    int h = blockIdx.x, tx = threadIdx.x, ty = threadIdx.y;
    int ft = ty * 160 + tx;
    if (ft < D) xs[ft] = src[h * D + ft];
    __syncthreads();
    int n = blockIdx.y * 160 + tx;
    float acc = 0.f;
    int k0 = ty * 80;
#pragma unroll 8
    for (int k = k0; k < k0 + 80; k++) acc += xs[k] * W[k * D + n];
    part[ty][tx] = acc;
    __syncthreads();
    if (ty == 0) {
        float q = (part[0][tx] + part[1][tx] + part[2][tx] + part[3][tx] + bias[n]) *
                  0.11180339887498949f;
        qv[tx] = q;
    }
    __syncthreads();
    if (ty == 0) {
        int p = (n % HD) >> 1;
        float cc = g_qc[p], ss = g_qs[p];
        float e = qv[tx & ~1], o = qv[tx | 1];
        g_q[h * D + n] = (n & 1) ? (o * cc + e * ss) : (e * cc - o * ss);
    }
}

// ---------------- K projection: tf32 tensor-core GEMM + LN-fold + bias + rotation ----------------
// C[16384,320] = A'[16384,320] @ B[320,320]; grid (128, 5), 256 threads
#define GBM 128
#define GBN 64
#define GBK 32
__global__ void __launch_bounds__(256) k_gemm_tc(
    const float* __restrict__ Araw,      // cached_l (self) or memory (cross)
    int selfmode, int loff,              // loff = l*NHYP*TCACHE for stats
    const float* __restrict__ lnw, const float* __restrict__ lnb,
    const float* __restrict__ B, const float* __restrict__ bias) {
    __shared__ uint32_t As[GBM][GBK + 4];
    __shared__ uint32_t Bs[GBK][GBN + 8];
    __shared__ float sw[D], sb[D];
    int tid = threadIdx.x;
    if (selfmode) {
        for (int i = tid; i < D; i += 256) {
            sw[i] = lnw[i];
            sb[i] = lnb[i];
        }
    }
    __syncthreads();
    int m0 = blockIdx.x * GBM, n0 = blockIdx.y * GBN;
    int warp = tid >> 5, lane = tid & 31;
    int wm = warp >> 1, wn = warp & 1;
    int g = lane >> 2, c = lane & 3;
    float acc[2][4][4];
#pragma unroll
    for (int a = 0; a < 2; a++)
#pragma unroll
        for (int bb = 0; bb < 4; bb++)
#pragma unroll
            for (int cc = 0; cc < 4; cc++) acc[a][bb][cc] = 0.f;

    for (int k0 = 0; k0 < D; k0 += GBK) {
#pragma unroll
        for (int i = 0; i < 4; i++) {
            int idx = tid + 256 * i;
            int row = idx >> 3, c4 = (idx & 7) * 4;
            int m = m0 + row;
            float4 v;
            if (selfmode) {
                int hyp = m >> 8, t = m & 255;
                if (t < TCACHE) {
                    int r = hyp * TCACHE + t;
                    v = *(const float4*)&Araw[(long)r * D + k0 + c4];
                    float m_ = g_mu[loff + r], rr = g_rs[loff + r];
                    v.x = (v.x - m_) * rr * sw[k0 + c4 + 0] + sb[k0 + c4 + 0];
                    v.y = (v.y - m_) * rr * sw[k0 + c4 + 1] + sb[k0 + c4 + 1];
                    v.z = (v.z - m_) * rr * sw[k0 + c4 + 2] + sb[k0 + c4 + 2];
                    v.w = (v.w - m_) * rr * sw[k0 + c4 + 3] + sb[k0 + c4 + 3];
                } else {
                    v = *(const float4*)&g_nt0[hyp * D + k0 + c4];
                }
            } else {
                v = *(const float4*)&Araw[(long)m * D + k0 + c4];
            }
            As[row][c4 + 0] = f2tf(v.x);
            As[row][c4 + 1] = f2tf(v.y);
            As[row][c4 + 2] = f2tf(v.z);
            As[row][c4 + 3] = f2tf(v.w);
        }
#pragma unroll
        for (int i = 0; i < 2; i++) {
            int idx = tid + 256 * i;
            int row = idx >> 4, n4 = (idx & 15) * 4;
            float4 v = *(const float4*)&B[(long)(k0 + row) * D + n0 + n4];
            Bs[row][n4 + 0] = f2tf(v.x);
            Bs[row][n4 + 1] = f2tf(v.y);
            Bs[row][n4 + 2] = f2tf(v.z);
            Bs[row][n4 + 3] = f2tf(v.w);
        }
        __syncthreads();
#pragma unroll
        for (int ks = 0; ks < 4; ks++) {
            uint32_t afr[2][4], bfr[4][2];
#pragma unroll
            for (int mi = 0; mi < 2; mi++) {
                int r = wm * 32 + mi * 16;
                afr[mi][0] = As[r + g][ks * 8 + c];
                afr[mi][1] = As[r + g + 8][ks * 8 + c];
                afr[mi][2] = As[r + g][ks * 8 + c + 4];
                afr[mi][3] = As[r + g + 8][ks * 8 + c + 4];
            }
#pragma unroll
            for (int ni = 0; ni < 4; ni++) {
                int nn = wn * 32 + ni * 8;
                bfr[ni][0] = Bs[ks * 8 + c][nn + g];
                bfr[ni][1] = Bs[ks * 8 + c + 4][nn + g];
            }
#pragma unroll
            for (int mi = 0; mi < 2; mi++)
#pragma unroll
                for (int ni = 0; ni < 4; ni++) mma_tf32(acc[mi][ni], afr[mi], bfr[ni]);
        }
        __syncthreads();
    }
#pragma unroll
    for (int mi = 0; mi < 2; mi++) {
#pragma unroll
        for (int ni = 0; ni < 4; ni++) {
            int nn = n0 + wn * 32 + ni * 8 + 2 * c;
            int p = (nn % HD) >> 1;
            float be = bias[nn], bo = bias[nn + 1];
            int r0 = m0 + wm * 32 + mi * 16 + g;
            int r1 = r0 + 8;
            {
                int t = r0 & 255;
                float cc = g_rotc[t * HALF + p], ss = g_rots[t * HALF + p];
                float e = acc[mi][ni][0] + be, o = acc[mi][ni][1] + bo;
                float2 st = make_float2(e * cc - o * ss, o * cc + e * ss);
                *(float2*)&g_k[(long)r0 * D + nn] = st;
            }
            {
                int t = r1 & 255;
                float cc = g_rotc[t * HALF + p], ss = g_rots[t * HALF + p];
                float e = acc[mi][ni][2] + be, o = acc[mi][ni][3] + bo;
                float2 st = make_float2(e * cc - o * ss, o * cc + e * ss);
                *(float2*)&g_k[(long)r1 * D + nn] = st;
            }
        }
    }
}

// ---------------- attention: scores + softmax + y = p @ X (LN folded) ----------------
// block 320 threads, grid 64
__global__ void k_attn(const float* __restrict__ X, int selfmode, int loff,
                       const float* __restrict__ lnw, const float* __restrict__ lnb,
                       const unsigned char* __restrict__ mask) {
    __shared__ float qs[D];
    __shared__ float p[NH][TK];
    __shared__ float buf[10];
    int h = blockIdx.x, tid = threadIdx.x;
    int warp = tid >> 5, lane = tid & 31;
    qs[tid] = g_q[h * D + tid];
    __syncthreads();
    for (int i = 0; i < 26; i++) {
        int t = warp * 26 + i;
        if (t < TK) {
            const float* kr = &g_k[((long)(h << 8) + t) * D];
            float sc[NH];
#pragma unroll
            for (int hh = 0; hh < NH; hh++) {
                int d0 = hh * HD + lane;
                float s = qs[d0] * kr[d0] + qs[d0 + 32] * kr[d0 + 32];
                if (lane < 16) s += qs[d0 + 64] * kr[d0 + 64];
                sc[hh] = s;
            }
#pragma unroll
            for (int hh = 0; hh < NH; hh++)
#pragma unroll
                for (int o = 16; o; o >>= 1) sc[hh] += __shfl_xor_sync(0xffffffffu, sc[hh], o);
            if (lane == 0) {
                bool msk = (mask != nullptr) && (mask[h * TK + t] != 0);
#pragma unroll
                for (int hh = 0; hh < NH; hh++) p[hh][t] = msk ? -1e30f : sc[hh];
            }
        }
    }
    __syncthreads();
    for (int hh = 0; hh < NH; hh++) {
        float lv = (tid < TK) ? p[hh][tid] : -1e30f;
        float mx = bmax(lv, buf, 10);
        float ex = (tid < TK) ? expf(lv - mx) : 0.f;
        float sm = bsum(ex, buf, 10);
        if (tid < TK) p[hh][tid] = ex / sm;
        __syncthreads();
    }
    float corrh[NH] = {0.f, 0.f, 0.f, 0.f};
    if (selfmode) {
        float muv = 0.f, rst = 0.f;
        if (tid < TCACHE) {
            int r = loff + h * TCACHE + tid;
            muv = g_mu[r];
            rst = g_rs[r];
        }
#pragma unroll
        for (int hh = 0; hh < NH; hh++) {
            float pv = (tid < TCACHE) ? p[hh][tid] : 0.f;
            corrh[hh] = bsum(pv * muv * rst, buf, 10);
        }
        if (tid < TCACHE) {
#pragma unroll
            for (int hh = 0; hh < NH; hh++) p[hh][tid] *= rst;
        }
        __syncthreads();
    }
    int col = tid;
    float a0 = 0.f, a1 = 0.f, a2 = 0.f, a3 = 0.f;
    if (selfmode) {
        const float* base = X + (long)h * TCACHE * D + col;
        for (int t = 0; t < TCACHE; t++) {
            float xv = base[(long)t * D];
            a0 += p[0][t] * xv;
            a1 += p[1][t] * xv;
            a2 += p[2][t] * xv;
            a3 += p[3][t] * xv;
        }
        float w = lnw[col], b = lnb[col], nv = g_nt0[h * D + col];
        float p0 = p[0][TCACHE], p1 = p[1][TCACHE], p2 = p[2][TCACHE], p3 = p[3][TCACHE];
        g_y[(h * NH + 0) * D + col] = (a0 - corrh[0]) * w + (1.f - p0) * b + p0 * nv;
        g_y[(h * NH + 1) * D + col] = (a1 - corrh[1]) * w + (1.f - p1) * b + p1 * nv;
        g_y[(h * NH + 2) * D + col] = (a2 - corrh[2]) * w + (1.f - p2) * b + p2 * nv;
        g_y[(h * NH + 3) * D + col] = (a3 - corrh[3]) * w + (1.f - p3) * b + p3 * nv;
    } else {
        const float* base = X + (long)h * TK * D + col;
        for (int t = 0; t < TK; t++) {
            float xv = base[(long)t * D];
            a0 += p[0][t] * xv;
            a1 += p[1][t] * xv;
            a2 += p[2][t] * xv;
            a3 += p[3][t] * xv;
        }
        g_y[(h * NH + 0) * D + col] = a0;
        g_y[(h * NH + 1) * D + col] = a1;
        g_y[(h * NH + 2) * D + col] = a2;
        g_y[(h * NH + 3) * D + col] = a3;
    }
}

// ---------------- out projection ----------------
// grid 64, block (320, 2)
__global__ void k_outproj(const float* __restrict__ Wv, const float* __restrict__ bv,
                          const float* __restrict__ Wo, const float* __restrict__ bo) {
    __shared__ float ys[NH * D];
    __shared__ float part[2][D];
    __shared__ float zs[D];
    int h = blockIdx.x, tx = threadIdx.x, ty = threadIdx.y;
    int ft = ty * D + tx;
    ys[ft] = g_y[h * NH * D + ft];
    ys[ft + 2 * D] = g_y[h * NH * D + ft + 2 * D];
    __syncthreads();
    int hh = tx / HD;
    float z = 0.f;
    const float* yb = &ys[hh * D];
    int d0 = ty * 160;
#pragma unroll 8
    for (int d2 = d0; d2 < d0 + 160; d2++) z += yb[d2] * Wv[d2 * D + tx];
    part[ty][tx] = z;
    __syncthreads();
    if (ty == 0) zs[tx] = part[0][tx] + part[1][tx] + bv[tx];
    __syncthreads();
    float o = 0.f;
    int m0 = ty * 160;
#pragma unroll 8
    for (int m = m0; m < m0 + 160; m++) o += zs[m] * Wo[m * D + tx];
    part[ty][tx] = o;
    __syncthreads();
    if (ty == 0) g_tgt[h * D + tx] += part[0][tx] + part[1][tx] + bo[tx];
}

// ---------------- FFN: hyp-batched tiled SIMT GEMM ----------------
// mode 0: g_ff = relu(g_nt @ W1 + b1)   (K=D, N=FF)
// mode 1: g_tgt += g_ff @ W2 + b2       (K=FF, N=D)
__global__ void __launch_bounds__(256) k_ffgemm(int K, const float* __restrict__ W, int N,
                                                const float* __restrict__ bias, int mode) {
    __shared__ float Asm[16][33];
    __shared__ float Wsm[32][68];
    const float* A = mode ? g_ff : g_nt;
    float* out = mode ? g_tgt : g_ff;
    int h0 = blockIdx.x * 16, n0 = blockIdx.y * 64;
    int tid = threadIdx.x, tx = tid & 15, ty = tid >> 4;
    float acc0 = 0.f, acc1 = 0.f, acc2 = 0.f, acc3 = 0.f;
    for (int k0 = 0; k0 < K; k0 += 32) {
        {
            int r = tid >> 5, kk = tid & 31;
            Asm[r][kk] = A[(long)(h0 + r) * K + k0 + kk];
            Asm[r + 8][kk] = A[(long)(h0 + r + 8) * K + k0 + kk];
#pragma unroll
            for (int i = 0; i < 2; i++) {
                int id2 = tid + 256 * i;
                int rr = id2 >> 4, c4 = (id2 & 15) * 4;
                float4 v = *(const float4*)&W[(long)(k0 + rr) * N + n0 + c4];
                Wsm[rr][c4 + 0] = v.x;
                Wsm[rr][c4 + 1] = v.y;
                Wsm[rr][c4 + 2] = v.z;
                Wsm[rr][c4 + 3] = v.w;
            }
        }
        __syncthreads();
#pragma unroll
        for (int k = 0; k < 32; k++) {
            float a = Asm[ty][k];
            acc0 += a * Wsm[k][tx * 4 + 0];
            acc1 += a * Wsm[k][tx * 4 + 1];
            acc2 += a * Wsm[k][tx * 4 + 2];
            acc3 += a * Wsm[k][tx * 4 + 3];
        }
        __syncthreads();
    }
    int row = h0 + ty, n = n0 + tx * 4;
    float* op = &out[(long)row * N + n];
    if (mode == 0) {
        op[0] = fmaxf(acc0 + bias[n + 0], 0.f);
        op[1] = fmaxf(acc1 + bias[n + 1], 0.f);
        op[2] = fmaxf(acc2 + bias[n + 2], 0.f);
        op[3] = fmaxf(acc3 + bias[n + 3], 0.f);
    } else {
        op[0] += acc0 + bias[n + 0];
        op[1] += acc1 + bias[n + 1];
        op[2] += acc2 + bias[n + 2];
        op[3] += acc3 + bias[n + 3];
    }
}

__global__ void k_copy_out(float* __restrict__ out) {
    out[blockIdx.x * D + threadIdx.x] = g_tgt[blockIdx.x * D + threadIdx.x];
}

// ---------------- launch ----------------
extern "C" void kernel_launch(void* const* d_in, const int* in_sizes, int n_in,
                              void* d_out, int out_size) {
    const int* toks = (const int*)d_in[0];
    const float* cached = (const float*)d_in[1];
    const float* memory = (const float*)d_in[2];
    const unsigned char* mmask = (const unsigned char*)d_in[3];
    const int* qoff = (const int*)d_in[4];
    const float* table = (const float*)d_in[5];
    const float* ln_w = (const float*)d_in[6];
    const float* ln_b = (const float*)d_in[7];
    const float* sa_w = (const float*)d_in[8];
    const float* sa_b = (const float*)d_in[9];
    const float* ca_w = (const float*)d_in[10];
    const float* ca_b = (const float*)d_in[11];
    const float* ff1w = (const float*)d_in[12];
    const float* ff1b = (const float*)d_in[13];
    const float* ff2w = (const float*)d_in[14];
    const float* ff2b = (const float*)d_in[15];

    k_tables<<<41, 256>>>(qoff);
    k_embed<<<NHYP, D>>>(toks, table);
    k_rowstats<<<(NL * NHYP * TCACHE + 7) / 8, 256>>>(cached);

    for (int l = 0; l < NL; l++) {
        const float* lw = ln_w + l * 3 * D;
        const float* lb = ln_b + l * 3 * D;
        const float* sw = sa_w + (long)l * 4 * D * D;
        const float* sb = sa_b + l * 4 * D;
        const float* cw = ca_w + (long)l * 4 * D * D;
        const float* cb = ca_b + l * 4 * D;
        const float* cache_l = cached + (long)l * NHYP * TCACHE * D;
        int loff = l * NHYP * TCACHE;

        // ---- self-attention ----
        k_ln_vec<<<NHYP, D>>>(lw, lb, 0);
        k_qproj<<<dim3(NHYP, 2), dim3(160, 4)>>>(0, sw + 0 * D * D, sb + 0 * D);
        k_gemm_tc<<<dim3(128, 5), 256>>>(cache_l, 1, loff, lw, lb, sw + 1 * D * D, sb + 1 * D);
        k_attn<<<NHYP, D>>>(cache_l, 1, loff, lw, lb, nullptr);
        k_outproj<<<NHYP, dim3(D, 2)>>>(sw + 2 * D * D, sb + 2 * D, sw + 3 * D * D, sb + 3 * D);

        // ---- cross-attention ----
        k_ln_vec<<<NHYP, D>>>(lw + D, lb + D, 1);
        k_qproj<<<dim3(NHYP, 2), dim3(160, 4)>>>(1, cw + 0 * D * D, cb + 0 * D);
        k_gemm_tc<<<dim3(128, 5), 256>>>(memory, 0, 0, nullptr, nullptr, cw + 1 * D * D, cb + 1 * D);
        k_attn<<<NHYP, D>>>(memory, 0, 0, nullptr, nullptr, mmask);
        k_outproj<<<NHYP, dim3(D, 2)>>>(cw + 2 * D * D, cb + 2 * D, cw + 3 * D * D, cb + 3 * D);

        // ---- feed-forward ----
        k_ln_vec<<<NHYP, D>>>(lw + 2 * D, lb + 2 * D, 1);
        k_ffgemm<<<dim3(4, FF / 64), 256>>>(D, ff1w + (long)l * D * FF, FF, ff1b + l * FF, 0);
        k_ffgemm<<<dim3(4, D / 64), 256>>>(FF, ff2w + (long)l * FF * D, D, ff2b + l * D, 1);
    }
    k_copy_out<<<NHYP, D>>>((float*)d_out);
}

// round 4
// speedup vs baseline: 1.6816x; 1.2620x over previous
#include <cuda_runtime.h>
#include <math.h>
#include <stdint.h>

#define NHYP 64
#define D 320
#define NH 4
#define HD 80
#define HALF 40
#define TK 256
#define TCACHE 255
#define FF 2048
#define NL 5

// ---------------- scratch (device globals) ----------------
__device__ float g_tgt[NHYP * D];
__device__ float g_nt0[NHYP * D];
__device__ float g_kself[NL * NHYP * TK * D];   // ~105 MB
__device__ float g_kcross[NL * NHYP * TK * D];  // ~105 MB
__device__ float g_q[NHYP * D];
__device__ float g_ff[NHYP * FF];
__device__ float g_mu[NL * NHYP * TCACHE];
__device__ float g_rs[NL * NHYP * TCACHE];
__device__ float g_rotc[TK * HALF];
__device__ float g_rots[TK * HALF];
__device__ float g_qc[HALF];
__device__ float g_qs[HALF];

// ---------------- helpers ----------------
__device__ __forceinline__ uint32_t f2tf(float f) {
    uint32_t u;
    asm("cvt.rna.tf32.f32 %0, %1;" : "=r"(u) : "f"(f));
    return u;
}
__device__ __forceinline__ void mma_tf32(float* d, const uint32_t* a, const uint32_t* b) {
    asm volatile(
        "mma.sync.aligned.m16n8k8.row.col.f32.tf32.tf32.f32 "
        "{%0,%1,%2,%3}, {%4,%5,%6,%7}, {%8,%9}, {%0,%1,%2,%3};"
        : "+f"(d[0]), "+f"(d[1]), "+f"(d[2]), "+f"(d[3])
        : "r"(a[0]), "r"(a[1]), "r"(a[2]), "r"(a[3]), "r"(b[0]), "r"(b[1]));
}

// ---------------- xPos tables ----------------
__global__ void k_tables(const int* __restrict__ qoff) {
    int e = blockIdx.x * blockDim.x + threadIdx.x;
    if (e < TK * HALF) {
        int t = e / HALF, i = e % HALF;
        float bs = (2.0f * i + 0.4f * HD) / (1.4f * HD);
        float invf = powf(10000.0f, -(float)i / HALF);
        float power = ((float)t - 128.0f) / 320.0f;
        float z = powf(bs, -power);
        float th = (float)t * invf;
        g_rotc[e] = cosf(th) * z;
        g_rots[e] = sinf(th) * z;
    } else if (e < TK * HALF + HALF) {
        int i = e - TK * HALF;
        int off = qoff[0];
        int total = off + 1;
        int minp = -((total + 1) >> 1);
        float bs = (2.0f * i + 0.4f * HD) / (1.4f * HD);
        float invf = powf(10000.0f, -(float)i / HALF);
        float pq = (float)(minp + total - 1) / 320.0f;
        float z = powf(bs, pq);
        float th = (float)(total - 1) * invf;
        g_qc[i] = cosf(th) * z;
        g_qs[i] = sinf(th) * z;
    }
}

__global__ void k_embed(const int* __restrict__ toks, const float* __restrict__ table) {
    int h = blockIdx.x, d = threadIdx.x;
    g_tgt[h * D + d] = table[(long)toks[h] * D + d];
}

// ---------------- per-row LN stats for all layers' caches ----------------
__global__ void k_rowstats(const float* __restrict__ cached) {
    int row = blockIdx.x * 8 + (threadIdx.x >> 5);
    if (row >= NL * NHYP * TCACHE) return;
    int lane = threadIdx.x & 31;
    const float* p = cached + (long)row * D;
    float s = 0.f, s2 = 0.f;
    for (int j = lane; j < D; j += 32) {
        float v = p[j];
        s += v;
        s2 += v * v;
    }
#pragma unroll
    for (int o = 16; o; o >>= 1) {
        s += __shfl_xor_sync(0xffffffffu, s, o);
        s2 += __shfl_xor_sync(0xffffffffu, s2, o);
    }
    if (lane == 0) {
        float mu = s * (1.0f / D);
        float var = s2 * (1.0f / D) - mu * mu;
        g_mu[row] = mu;
        g_rs[row] = rsqrtf(var + 1e-5f);
    }
}

// ---------------- batched K-projection GEMM: all 10 at once ----------------
// grid (128, 5, 10): z<5 -> self layer z; z>=5 -> cross layer z-5
#define GBM 128
#define GBN 64
#define GBK 32
__global__ void __launch_bounds__(256) k_gemm_all(
    const float* __restrict__ cached, const float* __restrict__ memory,
    const float* __restrict__ ln_w, const float* __restrict__ ln_b,
    const float* __restrict__ sa_w, const float* __restrict__ sa_b,
    const float* __restrict__ ca_w, const float* __restrict__ ca_b) {
    __shared__ uint32_t As[GBM][GBK + 4];
    __shared__ uint32_t Bs[GBK][GBN + 8];
    __shared__ float sw[D], sb[D];
    int z = blockIdx.z;
    bool selfmode = (z < 5);
    int l = selfmode ? z : z - 5;
    const float* Araw = selfmode ? cached + (long)l * NHYP * TCACHE * D : memory;
    const float* B = (selfmode ? sa_w : ca_w) + (long)l * 4 * D * D + D * D;
    const float* bias = (selfmode ? sa_b : ca_b) + l * 4 * D + D;
    float* out = (selfmode ? g_kself : g_kcross) + (long)l * NHYP * TK * D;
    int loff = l * NHYP * TCACHE;
    int tid = threadIdx.x;
    if (selfmode) {
        const float* lw = ln_w + l * 3 * D;
        const float* lb = ln_b + l * 3 * D;
        for (int i = tid; i < D; i += 256) {
            sw[i] = lw[i];
            sb[i] = lb[i];
        }
    }
    __syncthreads();
    int m0 = blockIdx.x * GBM, n0 = blockIdx.y * GBN;
    int warp = tid >> 5, lane = tid & 31;
    int wm = warp >> 1, wn = warp & 1;
    int g = lane >> 2, c = lane & 3;
    float acc[2][4][4];
#pragma unroll
    for (int a = 0; a < 2; a++)
#pragma unroll
        for (int bb = 0; bb < 4; bb++)
#pragma unroll
            for (int cc = 0; cc < 4; cc++) acc[a][bb][cc] = 0.f;

    for (int k0 = 0; k0 < D; k0 += GBK) {
#pragma unroll
        for (int i = 0; i < 4; i++) {
            int idx = tid + 256 * i;
            int row = idx >> 3, c4 = (idx & 7) * 4;
            int m = m0 + row;
            float4 v = make_float4(0.f, 0.f, 0.f, 0.f);
            if (selfmode) {
                int hyp = m >> 8, t = m & 255;
                if (t < TCACHE) {
                    int r = hyp * TCACHE + t;
                    v = *(const float4*)&Araw[(long)r * D + k0 + c4];
                    float m_ = g_mu[loff + r], rr = g_rs[loff + r];
                    v.x = (v.x - m_) * rr * sw[k0 + c4 + 0] + sb[k0 + c4 + 0];
                    v.y = (v.y - m_) * rr * sw[k0 + c4 + 1] + sb[k0 + c4 + 1];
                    v.z = (v.z - m_) * rr * sw[k0 + c4 + 2] + sb[k0 + c4 + 2];
                    v.w = (v.w - m_) * rr * sw[k0 + c4 + 3] + sb[k0 + c4 + 3];
                }  // t==255: zeros (overwritten per layer by k_qk)
            } else {
                v = *(const float4*)&Araw[(long)m * D + k0 + c4];
            }
            As[row][c4 + 0] = f2tf(v.x);
            As[row][c4 + 1] = f2tf(v.y);
            As[row][c4 + 2] = f2tf(v.z);
            As[row][c4 + 3] = f2tf(v.w);
        }
#pragma unroll
        for (int i = 0; i < 2; i++) {
            int idx = tid + 256 * i;
            int row = idx >> 4, n4 = (idx & 15) * 4;
            float4 v = *(const float4*)&B[(long)(k0 + row) * D + n0 + n4];
            Bs[row][n4 + 0] = f2tf(v.x);
            Bs[row][n4 + 1] = f2tf(v.y);
            Bs[row][n4 + 2] = f2tf(v.z);
            Bs[row][n4 + 3] = f2tf(v.w);
        }
        __syncthreads();
#pragma unroll
        for (int ks = 0; ks < 4; ks++) {
            uint32_t afr[2][4], bfr[4][2];
#pragma unroll
            for (int mi = 0; mi < 2; mi++) {
                int r = wm * 32 + mi * 16;
                afr[mi][0] = As[r + g][ks * 8 + c];
                afr[mi][1] = As[r + g + 8][ks * 8 + c];
                afr[mi][2] = As[r + g][ks * 8 + c + 4];
                afr[mi][3] = As[r + g + 8][ks * 8 + c + 4];
            }
#pragma unroll
            for (int ni = 0; ni < 4; ni++) {
                int nn = wn * 32 + ni * 8;
                bfr[ni][0] = Bs[ks * 8 + c][nn + g];
                bfr[ni][1] = Bs[ks * 8 + c + 4][nn + g];
            }
#pragma unroll
            for (int mi = 0; mi < 2; mi++)
#pragma unroll
                for (int ni = 0; ni < 4; ni++) mma_tf32(acc[mi][ni], afr[mi], bfr[ni]);
        }
        __syncthreads();
    }
#pragma unroll
    for (int mi = 0; mi < 2; mi++) {
#pragma unroll
        for (int ni = 0; ni < 4; ni++) {
            int nn = n0 + wn * 32 + ni * 8 + 2 * c;
            int p = (nn % HD) >> 1;
            float be = bias[nn], bo = bias[nn + 1];
            int r0 = m0 + wm * 32 + mi * 16 + g;
            int r1 = r0 + 8;
            {
                int t = r0 & 255;
                float cc = g_rotc[t * HALF + p], ss = g_rots[t * HALF + p];
                float e = acc[mi][ni][0] + be, o = acc[mi][ni][1] + bo;
                float2 st = make_float2(e * cc - o * ss, o * cc + e * ss);
                *(float2*)&out[(long)r0 * D + nn] = st;
            }
            {
                int t = r1 & 255;
                float cc = g_rotc[t * HALF + p], ss = g_rots[t * HALF + p];
                float e = acc[mi][ni][2] + be, o = acc[mi][ni][3] + bo;
                float2 st = make_float2(e * cc - o * ss, o * cc + e * ss);
                *(float2*)&out[(long)r1 * D + nn] = st;
            }
        }
    }
}

// ---------------- fused LN + q-proj (+ k255-proj for self) ----------------
// grid (64, 2, selfmode?2:1), block (160, 4)
__global__ void k_qk(int selfmode, int l,
                     const float* __restrict__ lnw, const float* __restrict__ lnb,
                     const float* __restrict__ Wq, const float* __restrict__ bq,
                     const float* __restrict__ Wk, const float* __restrict__ bk) {
    __shared__ float xs[D];
    __shared__ float part[4][160];
    __shared__ float qv[160];
    __shared__ float red[20];
    __shared__ float mv[2];
    int h = blockIdx.x, tx = threadIdx.x, ty = threadIdx.y;
    int ft = ty * 160 + tx;
    int lane = ft & 31, warp = ft >> 5;
    float v = (ft < D) ? g_tgt[h * D + ft] : 0.f;
    float s = v;
#pragma unroll
    for (int o = 16; o; o >>= 1) s += __shfl_xor_sync(0xffffffffu, s, o);
    if (lane == 0) red[warp] = s;
    __syncthreads();
    if (ft == 0) {
        float a = 0.f;
        for (int i = 0; i < 20; i++) a += red[i];
        mv[0] = a * (1.0f / D);
    }
    __syncthreads();
    float mu = mv[0];
    float dv = v - mu;
    float q2 = (ft < D) ? dv * dv : 0.f;
#pragma unroll
    for (int o = 16; o; o >>= 1) q2 += __shfl_xor_sync(0xffffffffu, q2, o);
    if (lane == 0) red[warp] = q2;
    __syncthreads();
    if (ft == 0) {
        float a = 0.f;
        for (int i = 0; i < 20; i++) a += red[i];
        mv[1] = rsqrtf(a * (1.0f / D) + 1e-5f);
    }
    __syncthreads();
    if (ft < D) xs[ft] = dv * mv[1] * lnw[ft] + lnb[ft];
    __syncthreads();
    if (selfmode && blockIdx.y == 0 && blockIdx.z == 0 && ft < D)
        g_nt0[h * D + ft] = xs[ft];
    // projection
    const float* W = (blockIdx.z == 0) ? Wq : Wk;
    const float* bias = (blockIdx.z == 0) ? bq : bk;
    int n = blockIdx.y * 160 + tx;
    float acc = 0.f;
    int k0 = ty * 80;
#pragma unroll 8
    for (int k = k0; k < k0 + 80; k++) acc += xs[k] * W[k * D + n];
    part[ty][tx] = acc;
    __syncthreads();
    if (ty == 0) {
        float t = part[0][tx] + part[1][tx] + part[2][tx] + part[3][tx] + bias[n];
        qv[tx] = (blockIdx.z == 0) ? t * 0.11180339887498949f : t;
    }
    __syncthreads();
    if (ty == 0) {
        int p = (n % HD) >> 1;
        float cc, ss;
        if (blockIdx.z == 0) {
            cc = g_qc[p];
            ss = g_qs[p];
        } else {
            cc = g_rotc[TCACHE * HALF + p];
            ss = g_rots[TCACHE * HALF + p];
        }
        float e = qv[tx & ~1], o = qv[tx | 1];
        float r = (n & 1) ? (o * cc + e * ss) : (e * cc - o * ss);
        if (blockIdx.z == 0)
            g_q[h * D + n] = r;
        else
            g_kself[(long)l * NHYP * TK * D + ((long)h * TK + TCACHE) * D + n] = r;
    }
}

// ---------------- fused attention + out-projection ----------------
// grid 64, block (320, 2)
__global__ void k_attn_out(const float* __restrict__ X, int selfmode, int loff, int l,
                           const float* __restrict__ lnw, const float* __restrict__ lnb,
                           const unsigned char* __restrict__ mask,
                           const float* __restrict__ Wv, const float* __restrict__ bv,
                           const float* __restrict__ Wo, const float* __restrict__ bo) {
    __shared__ float qs[D];           // later reused as z
    __shared__ float p[NH][TK];
    __shared__ float ys[NH][D];
    __shared__ float py[2][NH][D];
    __shared__ float part[2][D];
    __shared__ float red[2][8];
    __shared__ float val[2];
    __shared__ float redc[4][4];
    __shared__ float corr[NH];
    int h = blockIdx.x, tx = threadIdx.x, ty = threadIdx.y;
    int ft = ty * 320 + tx;
    int warp = ft >> 5, lane = ft & 31;
    const float* K = (selfmode ? g_kself : g_kcross) + (long)l * NHYP * TK * D +
                     (long)h * TK * D;
    if (ty == 0) qs[tx] = g_q[h * D + tx];
    __syncthreads();
    // ---- scores: 20 warps x 13 rows ----
#pragma unroll
    for (int i = 0; i < 13; i++) {
        int t = warp * 13 + i;
        if (t < TK) {
            const float* kr = K + (long)t * D;
            float sc[NH];
#pragma unroll
            for (int hh = 0; hh < NH; hh++) {
                int d0 = hh * HD + lane;
                float s = qs[d0] * kr[d0] + qs[d0 + 32] * kr[d0 + 32];
                if (lane < 16) s += qs[d0 + 64] * kr[d0 + 64];
                sc[hh] = s;
            }
#pragma unroll
            for (int hh = 0; hh < NH; hh++)
#pragma unroll
                for (int o = 16; o; o >>= 1)
                    sc[hh] += __shfl_xor_sync(0xffffffffu, sc[hh], o);
            if (lane == 0) {
                bool msk = (mask != nullptr) && (mask[h * TK + t] != 0);
#pragma unroll
                for (int hh = 0; hh < NH; hh++) p[hh][t] = msk ? -1e30f : sc[hh];
            }
        }
    }
    __syncthreads();
    // ---- softmax: 2 passes, 2 heads per pass, 256-thread groups ----
    for (int pass = 0; pass < 2; pass++) {
        bool act = (ft < 512);
        int grp = (ft >> 8) & 1;
        int hh = pass * 2 + grp;
        int t = ft & 255;
        float lv = act ? p[hh][t] : -1e30f;
        float m = lv;
#pragma unroll
        for (int o = 16; o; o >>= 1) m = fmaxf(m, __shfl_xor_sync(0xffffffffu, m, o));
        if (act && lane == 0) red[grp][(ft >> 5) & 7] = m;
        __syncthreads();
        if (act && (ft & 255) == 0) {
            float mm = red[grp][0];
            for (int j = 1; j < 8; j++) mm = fmaxf(mm, red[grp][j]);
            val[grp] = mm;
        }
        __syncthreads();
        float ex = act ? expf(lv - val[grp]) : 0.f;
        float ssum = ex;
#pragma unroll
        for (int o = 16; o; o >>= 1) ssum += __shfl_xor_sync(0xffffffffu, ssum, o);
        if (act && lane == 0) red[grp][(ft >> 5) & 7] = ssum;
        __syncthreads();
        if (act && (ft & 255) == 0) {
            float ss = 0.f;
            for (int j = 0; j < 8; j++) ss += red[grp][j];
            val[grp] = ss;
        }
        __syncthreads();
        if (act) p[hh][t] = ex / val[grp];
        __syncthreads();
    }
    // ---- LN fold (self): p *= rs (t<255), corr[hh] = sum p'*mu ----
    if (selfmode) {
        float c1 = 0.f;
        if (ft < 512) {
            int hh = ft >> 7, t0 = ft & 127;
            int r = loff + h * TCACHE;
            float p0 = p[hh][t0] * g_rs[r + t0];
            c1 = p0 * g_mu[r + t0];
            p[hh][t0] = p0;
            if (t0 < 127) {
                float p1 = p[hh][t0 + 128] * g_rs[r + t0 + 128];
                c1 += p1 * g_mu[r + t0 + 128];
                p[hh][t0 + 128] = p1;
            }
        }
#pragma unroll
        for (int o = 16; o; o >>= 1) c1 += __shfl_xor_sync(0xffffffffu, c1, o);
        if (ft < 512 && lane == 0) redc[ft >> 7][(ft >> 5) & 3] = c1;
        __syncthreads();
        if (ft < 512 && (ft & 127) == 0) {
            int hh = ft >> 7;
            corr[hh] = redc[hh][0] + redc[hh][1] + redc[hh][2] + redc[hh][3];
        }
        __syncthreads();
    }
    // ---- y = p @ X, t-range split over ty ----
    {
        float a0 = 0.f, a1 = 0.f, a2 = 0.f, a3 = 0.f;
        int stride = selfmode ? TCACHE : TK;
        int tlo = ty * 128;
        int thi = ty ? stride : 128;
        const float* base = X + (long)h * stride * D + tx;
        for (int t = tlo; t < thi; t++) {
            float xv = base[(long)t * D];
            a0 += p[0][t] * xv;
            a1 += p[1][t] * xv;
            a2 += p[2][t] * xv;
            a3 += p[3][t] * xv;
        }
        py[ty][0][tx] = a0;
        py[ty][1][tx] = a1;
        py[ty][2][tx] = a2;
        py[ty][3][tx] = a3;
    }
    __syncthreads();
    if (ty == 0) {
        if (selfmode) {
            float w = lnw[tx], b = lnb[tx], nv = g_nt0[h * D + tx];
#pragma unroll
            for (int hh = 0; hh < NH; hh++) {
                float a = py[0][hh][tx] + py[1][hh][tx];
                float pf = p[hh][TCACHE];
                ys[hh][tx] = (a - corr[hh]) * w + (1.f - pf) * b + pf * nv;
            }
        } else {
#pragma unroll
            for (int hh = 0; hh < NH; hh++) ys[hh][tx] = py[0][hh][tx] + py[1][hh][tx];
        }
    }
    __syncthreads();
    // ---- z = y @ Wv + bv (per-head slice) ----
    {
        int hh = tx / HD;
        const float* yb = ys[hh];
        float z = 0.f;
        int d0 = ty * 160;
#pragma unroll 8
        for (int d2 = d0; d2 < d0 + 160; d2++) z += yb[d2] * Wv[d2 * D + tx];
        part[ty][tx] = z;
    }
    __syncthreads();
    if (ty == 0) qs[tx] = part[0][tx] + part[1][tx] + bv[tx];
    __syncthreads();
    // ---- out = z @ Wo + bo; tgt += ----
    {
        float o = 0.f;
        int m0 = ty * 160;
#pragma unroll 8
        for (int m = m0; m < m0 + 160; m++) o += qs[m] * Wo[m * D + tx];
        part[ty][tx] = o;
    }
    __syncthreads();
    if (ty == 0) g_tgt[h * D + tx] += part[0][tx] + part[1][tx] + bo[tx];
}

// ---------------- FF1 with fused LN ----------------
// grid (4, 32), block 256
__global__ void __launch_bounds__(256) k_ff1(const float* __restrict__ lnw,
                                             const float* __restrict__ lnb,
                                             const float* __restrict__ W1,
                                             const float* __restrict__ b1) {
    __shared__ float Aln[16][D + 1];
    __shared__ float Wsm[32][68];
    int h0 = blockIdx.x * 16, n0 = blockIdx.y * 64;
    int tid = threadIdx.x;
    int w = tid >> 5, lane = tid & 31;
#pragma unroll
    for (int rr = 0; rr < 2; rr++) {
        int row = w * 2 + rr;
        const float* src = g_tgt + (h0 + row) * D;
        float s = 0.f, s2 = 0.f;
        for (int j = lane; j < D; j += 32) {
            float x = src[j];
            s += x;
            s2 += x * x;
        }
#pragma unroll
        for (int o = 16; o; o >>= 1) {
            s += __shfl_xor_sync(0xffffffffu, s, o);
            s2 += __shfl_xor_sync(0xffffffffu, s2, o);
        }
        float mu = s * (1.0f / D);
        float rsd = rsqrtf(s2 * (1.0f / D) - mu * mu + 1e-5f);
        for (int j = lane; j < D; j += 32)
            Aln[row][j] = (src[j] - mu) * rsd * lnw[j] + lnb[j];
    }
    __syncthreads();
    int tx = tid & 15, ty = tid >> 4;
    float acc0 = 0.f, acc1 = 0.f, acc2 = 0.f, acc3 = 0.f;
    for (int k0 = 0; k0 < D; k0 += 32) {
#pragma unroll
        for (int i = 0; i < 2; i++) {
            int id2 = tid + 256 * i;
            int rr = id2 >> 4, c4 = (id2 & 15) * 4;
            float4 v = *(const float4*)&W1[(long)(k0 + rr) * FF + n0 + c4];
            Wsm[rr][c4 + 0] = v.x;
            Wsm[rr][c4 + 1] = v.y;
            Wsm[rr][c4 + 2] = v.z;
            Wsm[rr][c4 + 3] = v.w;
        }
        __syncthreads();
#pragma unroll
        for (int k = 0; k < 32; k++) {
            float a = Aln[ty][k0 + k];
            acc0 += a * Wsm[k][tx * 4 + 0];
            acc1 += a * Wsm[k][tx * 4 + 1];
            acc2 += a * Wsm[k][tx * 4 + 2];
            acc3 += a * Wsm[k][tx * 4 + 3];
        }
        __syncthreads();
    }
    int row = h0 + ty, n = n0 + tx * 4;
    float* op = &g_ff[(long)row * FF + n];
    op[0] = fmaxf(acc0 + b1[n + 0], 0.f);
    op[1] = fmaxf(acc1 + b1[n + 1], 0.f);
    op[2] = fmaxf(acc2 + b1[n + 2], 0.f);
    op[3] = fmaxf(acc3 + b1[n + 3], 0.f);
}

// ---------------- FF2 with K-split + atomicAdd ----------------
// grid (4, 5, 4), block 256
__global__ void __launch_bounds__(256) k_ff2(const float* __restrict__ W2,
                                             const float* __restrict__ b2) {
    __shared__ float Asm[16][33];
    __shared__ float Wsm[32][68];
    int h0 = blockIdx.x * 16, n0 = blockIdx.y * 64, kz = blockIdx.z;
    int tid = threadIdx.x, tx = tid & 15, ty = tid >> 4;
    float acc0 = 0.f, acc1 = 0.f, acc2 = 0.f, acc3 = 0.f;
    for (int k0 = kz * 512; k0 < kz * 512 + 512; k0 += 32) {
        {
            int r = tid >> 5, kk = tid & 31;
            Asm[r][kk] = g_ff[(long)(h0 + r) * FF + k0 + kk];
            Asm[r + 8][kk] = g_ff[(long)(h0 + r + 8) * FF + k0 + kk];
#pragma unroll
            for (int i = 0; i < 2; i++) {
                int id2 = tid + 256 * i;
                int rr = id2 >> 4, c4 = (id2 & 15) * 4;
                float4 v = *(const float4*)&W2[(long)(k0 + rr) * D + n0 + c4];
                Wsm[rr][c4 + 0] = v.x;
                Wsm[rr][c4 + 1] = v.y;
                Wsm[rr][c4 + 2] = v.z;
                Wsm[rr][c4 + 3] = v.w;
            }
        }
        __syncthreads();
#pragma unroll
        for (int k = 0; k < 32; k++) {
            float a = Asm[ty][k];
            acc0 += a * Wsm[k][tx * 4 + 0];
            acc1 += a * Wsm[k][tx * 4 + 1];
            acc2 += a * Wsm[k][tx * 4 + 2];
            acc3 += a * Wsm[k][tx * 4 + 3];
        }
        __syncthreads();
    }
    int row = h0 + ty, n = n0 + tx * 4;
    if (kz == 0) {
        acc0 += b2[n + 0];
        acc1 += b2[n + 1];
        acc2 += b2[n + 2];
        acc3 += b2[n + 3];
    }
    atomicAdd(&g_tgt[row * D + n + 0], acc0);
    atomicAdd(&g_tgt[row * D + n + 1], acc1);
    atomicAdd(&g_tgt[row * D + n + 2], acc2);
    atomicAdd(&g_tgt[row * D + n + 3], acc3);
}

__global__ void k_copy_out(float* __restrict__ out) {
    out[blockIdx.x * D + threadIdx.x] = g_tgt[blockIdx.x * D + threadIdx.x];
}

// ---------------- launch ----------------
extern "C" void kernel_launch(void* const* d_in, const int* in_sizes, int n_in,
                              void* d_out, int out_size) {
    const int* toks = (const int*)d_in[0];
    const float* cached = (const float*)d_in[1];
    const float* memory = (const float*)d_in[2];
    const unsigned char* mmask = (const unsigned char*)d_in[3];
    const int* qoff = (const int*)d_in[4];
    const float* table = (const float*)d_in[5];
    const float* ln_w = (const float*)d_in[6];
    const float* ln_b = (const float*)d_in[7];
    const float* sa_w = (const float*)d_in[8];
    const float* sa_b = (const float*)d_in[9];
    const float* ca_w = (const float*)d_in[10];
    const float* ca_b = (const float*)d_in[11];
    const float* ff1w = (const float*)d_in[12];
    const float* ff1b = (const float*)d_in[13];
    const float* ff2w = (const float*)d_in[14];
    const float* ff2b = (const float*)d_in[15];

    k_tables<<<41, 256>>>(qoff);
    k_embed<<<NHYP, D>>>(toks, table);
    k_rowstats<<<(NL * NHYP * TCACHE + 7) / 8, 256>>>(cached);
    k_gemm_all<<<dim3(128, 5, 10), 256>>>(cached, memory, ln_w, ln_b, sa_w, sa_b,
                                          ca_w, ca_b);

    for (int l = 0; l < NL; l++) {
        const float* lw = ln_w + l * 3 * D;
        const float* lb = ln_b + l * 3 * D;
        const float* sw = sa_w + (long)l * 4 * D * D;
        const float* sb = sa_b + l * 4 * D;
        const float* cw = ca_w + (long)l * 4 * D * D;
        const float* cb = ca_b + l * 4 * D;
        const float* cache_l = cached + (long)l * NHYP * TCACHE * D;
        int loff = l * NHYP * TCACHE;

        // ---- self-attention ----
        k_qk<<<dim3(NHYP, 2, 2), dim3(160, 4)>>>(1, l, lw, lb, sw, sb,
                                                 sw + D * D, sb + D);
        k_attn_out<<<NHYP, dim3(320, 2)>>>(cache_l, 1, loff, l, lw, lb, nullptr,
                                           sw + 2 * D * D, sb + 2 * D,
                                           sw + 3 * D * D, sb + 3 * D);
        // ---- cross-attention ----
        k_qk<<<dim3(NHYP, 2, 1), dim3(160, 4)>>>(0, l, lw + D, lb + D, cw, cb,
                                                 nullptr, nullptr);
        k_attn_out<<<NHYP, dim3(320, 2)>>>(memory, 0, 0, l, nullptr, nullptr, mmask,
                                           cw + 2 * D * D, cb + 2 * D,
                                           cw + 3 * D * D, cb + 3 * D);
        // ---- feed-forward ----
        k_ff1<<<dim3(4, FF / 64), 256>>>(lw + 2 * D, lb + 2 * D,
                                         ff1w + (long)l * D * FF, ff1b + l * FF);
        k_ff2<<<dim3(4, 5, 4), 256>>>(ff2w + (long)l * FF * D, ff2b + l * D);
    }
    k_copy_out<<<NHYP, D>>>((float*)d_out);
}